// round 8
// baseline (speedup 1.0000x reference)
#include <cuda_runtime.h>
#include <stdint.h>

#define N_BOX 32768
#define C_CLS 81
#define K_TOP 4096
#define SCORE_T 0.05f
#define NMS_T 0.5f
#define IMG_W 1333.0f
#define IMG_H 800.0f
#define CLS_OFF 4096.0f

#define CAND_MAX (N_BOX * 20)   // provably <=19 candidates/row (probs sum to 1)
#define SEL_MAX 16384

// p in (0.05, 1.0]  =>  float top-16 bits in [0x3D4C, 0x3F80]
#define HIST_LO 0x3D4C
#define HIST_N  565

__device__ unsigned long long g_cand[CAND_MAX];
__device__ int g_cnt;
__device__ unsigned int g_hist[HIST_N];
__device__ int g_cutBucket;          // relative to HIST_LO
__device__ unsigned long long g_sel[SEL_MAX];
__device__ int g_selCnt;

__device__ float g_bk[K_TOP][4];
__device__ float g_boff[K_TOP][4];
__device__ float g_area[K_TOP];
__device__ float g_val[K_TOP];
__device__ int   g_label[K_TOP];

__device__ unsigned long long g_mask[K_TOP * 64];  // lower triangle never written: stays 0
__device__ unsigned long long g_rowAny[64];
__device__ unsigned long long g_removed[64];

// xor-butterfly tree sum — all lanes end with identical bits (VALIDATED)
__device__ __forceinline__ float btree_add(float v) {
    #pragma unroll
    for (int o = 16; o; o >>= 1) v = __fadd_rn(v, __shfl_xor_sync(0xFFFFFFFFu, v, o));
    return v;
}

__global__ void k_zero() {
    int t = threadIdx.x;
    if (t < HIST_N) g_hist[t] = 0u;
    if (t == 0) g_cnt = 0;
}

// one warp per row — bitwise model of the Triton/MLIR normalization emitter
// (VALIDATED round 6: rel_err 9.3e-12 — arithmetic is FROZEN)
__global__ void k_softmax(const float* __restrict__ x) {
    int warp = (blockIdx.x * blockDim.x + threadIdx.x) >> 5;
    int lane = threadIdx.x & 31;
    if (warp >= N_BOX) return;
    const float* row = x + (size_t)warp * C_CLS;

    float v0 = row[lane];
    float v1 = row[lane + 32];
    float v2 = (lane < 17) ? row[lane + 64] : -1e30f;

    float m = fmaxf(fmaxf(v0, v1), v2);
    #pragma unroll
    for (int o = 16; o; o >>= 1) m = fmaxf(m, __shfl_xor_sync(0xFFFFFFFFu, m, o));

    float e0 = expf(__fsub_rn(v0, m));
    float e1 = expf(__fsub_rn(v1, m));
    float e2 = (lane < 17) ? expf(__fsub_rn(v2, m)) : 0.0f;

    float B0 = btree_add(e0);
    float B1 = btree_add(e1);
    float B2 = btree_add(e2);
    float s = __fadd_rn(__fadd_rn(B0, B2), B1);

    float p0 = __fdiv_rn(e0, s);
    float p1 = __fdiv_rn(e1, s);
    float p2 = __fdiv_rn(e2, s);

    bool val0 = (lane != 0) && (p0 > SCORE_T);
    bool val1 = (p1 > SCORE_T);                    // c = lane+32, always 1..80? (33..63 yes)
    bool val2 = (lane < 17) && (p2 > SCORE_T);

    unsigned bal0 = __ballot_sync(0xFFFFFFFFu, val0);
    unsigned bal1 = __ballot_sync(0xFFFFFFFFu, val1);
    unsigned bal2 = __ballot_sync(0xFFFFFFFFu, val2);
    int n0 = __popc(bal0), n1 = __popc(bal1), n2 = __popc(bal2);
    int tot = n0 + n1 + n2;
    int base = 0;
    if (lane == 0 && tot) base = atomicAdd(&g_cnt, tot);
    base = __shfl_sync(0xFFFFFFFFu, base, 0);
    unsigned lmask = (1u << lane) - 1u;
    unsigned rowbase = (unsigned)warp * C_CLS;

    if (val0) {
        unsigned vb = __float_as_uint(p0);
        g_cand[base + __popc(bal0 & lmask)] =
            ((unsigned long long)vb << 32) | (0xFFFFFFFFu - (rowbase + lane));
        atomicAdd(&g_hist[(vb >> 16) - HIST_LO], 1u);
    }
    if (val1) {
        unsigned vb = __float_as_uint(p1);
        g_cand[base + n0 + __popc(bal1 & lmask)] =
            ((unsigned long long)vb << 32) | (0xFFFFFFFFu - (rowbase + lane + 32));
        atomicAdd(&g_hist[(vb >> 16) - HIST_LO], 1u);
    }
    if (val2) {
        unsigned vb = __float_as_uint(p2);
        g_cand[base + n0 + n1 + __popc(bal2 & lmask)] =
            ((unsigned long long)vb << 32) | (0xFFFFFFFFu - (rowbase + lane + 64));
        atomicAdd(&g_hist[(vb >> 16) - HIST_LO], 1u);
    }
}

// find cut bucket; also zero selCnt / rowAny for the downstream kernels
__global__ void k_findcut() {
    __shared__ unsigned int h[HIST_N];
    int t = threadIdx.x;
    if (t < HIST_N) h[t] = g_hist[t];
    if (t == 0) g_selCnt = 0;
    if (t < 64) g_rowAny[t] = 0ull;
    __syncthreads();
    if (t == 0) {
        unsigned int acc = 0;
        int b = HIST_N - 1;
        for (; b >= 0; b--) {
            acc += h[b];
            if (acc >= K_TOP) break;
        }
        g_cutBucket = (b < 0) ? 0 : b;
    }
}

__global__ void k_compact() {
    int cnt = g_cnt;
    int cut = g_cutBucket;
    int stride = gridDim.x * blockDim.x;
    for (int t = blockIdx.x * blockDim.x + threadIdx.x; t < cnt; t += stride) {
        unsigned long long key = g_cand[t];
        if ((int)((unsigned)(key >> 48) - HIST_LO) >= cut) {
            int pos = atomicAdd(&g_selCnt, 1);
            if (pos < SEL_MAX) g_sel[pos] = key;
        }
    }
}

// fused exact rank (descending, keys unique) + decode/scatter into final slot
__global__ void k_rankscatter(const float* __restrict__ boxes) {
    __shared__ unsigned long long tile[256];
    int m = g_selCnt; if (m > SEL_MAX) m = SEL_MAX;
    int i0 = blockIdx.x * 256;
    if (i0 >= m) return;                    // uniform per block
    int i = i0 + threadIdx.x;
    unsigned long long key = (i < m) ? g_sel[i] : 0ull;
    int cnt = 0;
    int ntile = (m + 255) >> 8;
    for (int tb = 0; tb < ntile; tb++) {
        int jt = tb * 256 + threadIdx.x;
        __syncthreads();
        tile[threadIdx.x] = (jt < m) ? g_sel[jt] : 0ull;
        __syncthreads();
        int lim = m - tb * 256; if (lim > 256) lim = 256;
        #pragma unroll 8
        for (int j = 0; j < lim; j++) cnt += (tile[j] > key);
    }
    if (i >= m || cnt >= K_TOP) return;
    int r = cnt;
    unsigned idx = 0xFFFFFFFFu - (unsigned)(key & 0xFFFFFFFFull);
    float val = __uint_as_float((unsigned)(key >> 32));
    int bi = (int)(idx / C_CLS);
    int lb = (int)(idx % C_CLS);
    float x1 = fminf(fmaxf(boxes[bi * 4 + 0], 0.0f), IMG_W - 1.0f);
    float y1 = fminf(fmaxf(boxes[bi * 4 + 1], 0.0f), IMG_H - 1.0f);
    float x2 = fminf(fmaxf(boxes[bi * 4 + 2], 0.0f), IMG_W - 1.0f);
    float y2 = fminf(fmaxf(boxes[bi * 4 + 3], 0.0f), IMG_H - 1.0f);
    g_bk[r][0] = x1; g_bk[r][1] = y1; g_bk[r][2] = x2; g_bk[r][3] = y2;
    g_val[r] = val; g_label[r] = lb;
    float off = __fmul_rn((float)lb, CLS_OFF);
    float ox1 = __fadd_rn(x1, off), oy1 = __fadd_rn(y1, off);
    float ox2 = __fadd_rn(x2, off), oy2 = __fadd_rn(y2, off);
    g_boff[r][0] = ox1; g_boff[r][1] = oy1; g_boff[r][2] = ox2; g_boff[r][3] = oy2;
    g_area[r] = __fmul_rn(__fsub_rn(ox2, ox1), __fsub_rn(oy2, oy1));
}

// suppression bitmask over the upper triangle only
__global__ void k_mask() {
    int q = blockIdx.x;
    int colB = (int)((sqrtf(8.0f * (float)q + 1.0f) - 1.0f) * 0.5f);
    while ((colB + 1) * (colB + 2) / 2 <= q) colB++;
    while (colB * (colB + 1) / 2 > q) colB--;
    int rowB = q - colB * (colB + 1) / 2;

    int t = threadIdx.x;  // 64 threads
    __shared__ float cb[64][4];
    __shared__ float ca[64];
    int j0 = colB * 64;
    cb[t][0] = g_boff[j0 + t][0]; cb[t][1] = g_boff[j0 + t][1];
    cb[t][2] = g_boff[j0 + t][2]; cb[t][3] = g_boff[j0 + t][3];
    ca[t] = g_area[j0 + t];
    __syncthreads();

    int i = rowB * 64 + t;
    unsigned long long w = 0ull;
    {
        float x1 = g_boff[i][0], y1 = g_boff[i][1], x2 = g_boff[i][2], y2 = g_boff[i][3];
        float ai = g_area[i];
        #pragma unroll 4
        for (int jj = 0; jj < 64; jj++) {
            int j = j0 + jj;
            if (j > i) {
                float iw = fmaxf(__fsub_rn(fminf(x2, cb[jj][2]), fmaxf(x1, cb[jj][0])), 0.0f);
                float ih = fmaxf(__fsub_rn(fminf(y2, cb[jj][3]), fmaxf(y1, cb[jj][1])), 0.0f);
                float inter = __fmul_rn(iw, ih);
                float denom = __fadd_rn(__fsub_rn(__fadd_rn(ai, ca[jj]), inter), 1e-9f);
                if (__fdiv_rn(inter, denom) > NMS_T) w |= (1ull << jj);
            }
        }
    }
    g_mask[(size_t)i * 64 + colB] = w;
    if (w) atomicOr(&g_rowAny[rowB], 1ull << t);
}

// fused: single-warp sequential greedy NMS (shfl-based, no barriers in loop),
// then all 1024 threads emit the output tensor
__global__ void k_seqout(float* __restrict__ out, int out_size) {
    __shared__ unsigned long long s_removed[64];
    __shared__ int list[K_TOP];
    __shared__ int s_nlist;
    int t = threadIdx.x;

    if (t == 0) {
        int n = 0;
        for (int w2 = 0; w2 < 64; w2++) {
            unsigned long long bits = g_rowAny[w2];
            while (bits) {
                int b = __ffsll((long long)bits) - 1;
                bits &= bits - 1ull;
                list[n++] = w2 * 64 + b;
            }
        }
        s_nlist = n;
    }
    __syncthreads();
    int n = s_nlist;

    if (t < 32) {
        // lane l owns removed words l and l+32
        unsigned long long r0 = 0ull, r1 = 0ull;
        unsigned long long p0 = 0ull, p1 = 0ull;
        float pv = 0.0f;
        if (n) {
            int i = list[0];
            p0 = g_mask[(size_t)i * 64 + t];
            p1 = g_mask[(size_t)i * 64 + t + 32];
            pv = g_val[i];
        }
        for (int k = 0; k < n; k++) {
            int i = list[k];
            unsigned long long c0 = p0, c1 = p1;
            float vi = pv;
            if (k + 1 < n) {
                int i2 = list[k + 1];
                p0 = g_mask[(size_t)i2 * 64 + t];
                p1 = g_mask[(size_t)i2 * 64 + t + 32];
                pv = g_val[i2];
            }
            int w = i >> 6;
            unsigned long long rv = (w < 32)
                ? __shfl_sync(0xFFFFFFFFu, r0, w)
                : __shfl_sync(0xFFFFFFFFu, r1, w - 32);
            if (!((rv >> (i & 63)) & 1ull) && vi > 0.0f) { r0 |= c0; r1 |= c1; }
        }
        s_removed[t] = r0;
        s_removed[t + 32] = r1;
    }
    __syncthreads();

    for (int o = t; o < out_size; o += blockDim.x) {
        float v = 0.0f;
        if (o < K_TOP * 5) {
            int r = o / 5, c = o - r * 5;
            bool keep = !((s_removed[r >> 6] >> (r & 63)) & 1ull) && (g_val[r] > 0.0f);
            if (keep) v = (c < 4) ? g_bk[r][c] : g_val[r];
        } else if (o < K_TOP * 6) {
            v = (float)g_label[o - K_TOP * 5];
        } else if (o < K_TOP * 7) {
            int r = o - K_TOP * 6;
            bool keep = !((s_removed[r >> 6] >> (r & 63)) & 1ull) && (g_val[r] > 0.0f);
            v = keep ? 1.0f : 0.0f;
        }
        out[o] = v;
    }
}

extern "C" void kernel_launch(void* const* d_in, const int* in_sizes, int n_in,
                              void* d_out, int out_size) {
    const float* x     = (const float*)d_in[0];
    const float* boxes = (const float*)d_in[1];
    float* out = (float*)d_out;

    k_zero<<<1, 576>>>();
    k_softmax<<<N_BOX / 8, 256>>>(x);
    k_findcut<<<1, 576>>>();
    k_compact<<<512, 256>>>();
    k_rankscatter<<<SEL_MAX / 256, 256>>>(boxes);
    k_mask<<<65 * 64 / 2, 64>>>();
    k_seqout<<<1, 1024>>>(out, out_size);
}

// round 9
// speedup vs baseline: 1.0774x; 1.0774x over previous
#include <cuda_runtime.h>
#include <stdint.h>

#define N_BOX 32768
#define C_CLS 81
#define K_TOP 4096
#define SCORE_T 0.05f
#define NMS_T 0.5f
#define IMG_W 1333.0f
#define IMG_H 800.0f
#define CLS_OFF 4096.0f

#define CAND_MAX (N_BOX * 20)   // provably <=19 candidates/row (probs sum to 1)
#define SEL_MAX 16384

// p in (0.05, 1.0]  =>  float top-16 bits in [0x3D4C, 0x3F80]
#define HIST_LO 0x3D4C
#define HIST_N  565

#define CLS_CAP 96   // max per-class rows-with-edges tracked in k_seqout

__device__ unsigned long long g_cand[CAND_MAX];
__device__ int g_cnt;
__device__ unsigned int g_hist[HIST_N];
__device__ int g_cutBucket;          // relative to HIST_LO
__device__ unsigned long long g_sel[SEL_MAX];
__device__ int g_selCnt;

__device__ float g_bk[K_TOP][4];
__device__ float g_boff[K_TOP][4];
__device__ float g_area[K_TOP];
__device__ float g_val[K_TOP];
__device__ int   g_label[K_TOP];

__device__ unsigned long long g_mask[K_TOP * 64];  // lower triangle never written: stays 0
__device__ unsigned long long g_rowAny[64];

// xor-butterfly tree sum — all lanes end with identical bits (VALIDATED)
__device__ __forceinline__ float btree_add(float v) {
    #pragma unroll
    for (int o = 16; o; o >>= 1) v = __fadd_rn(v, __shfl_xor_sync(0xFFFFFFFFu, v, o));
    return v;
}

__global__ void k_zero() {
    int t = threadIdx.x;
    if (t < HIST_N) g_hist[t] = 0u;
    if (t == 0) g_cnt = 0;
}

// one warp per row — bitwise model of the Triton/MLIR normalization emitter
// (VALIDATED round 6: rel_err 9.3e-12 — arithmetic is FROZEN)
__global__ void k_softmax(const float* __restrict__ x) {
    int warp = (blockIdx.x * blockDim.x + threadIdx.x) >> 5;
    int lane = threadIdx.x & 31;
    if (warp >= N_BOX) return;
    const float* row = x + (size_t)warp * C_CLS;

    float v0 = row[lane];
    float v1 = row[lane + 32];
    float v2 = (lane < 17) ? row[lane + 64] : -1e30f;

    float m = fmaxf(fmaxf(v0, v1), v2);
    #pragma unroll
    for (int o = 16; o; o >>= 1) m = fmaxf(m, __shfl_xor_sync(0xFFFFFFFFu, m, o));

    float e0 = expf(__fsub_rn(v0, m));
    float e1 = expf(__fsub_rn(v1, m));
    float e2 = (lane < 17) ? expf(__fsub_rn(v2, m)) : 0.0f;

    float B0 = btree_add(e0);
    float B1 = btree_add(e1);
    float B2 = btree_add(e2);
    float s = __fadd_rn(__fadd_rn(B0, B2), B1);

    float p0 = __fdiv_rn(e0, s);
    float p1 = __fdiv_rn(e1, s);
    float p2 = __fdiv_rn(e2, s);

    bool val0 = (lane != 0) && (p0 > SCORE_T);
    bool val1 = (p1 > SCORE_T);
    bool val2 = (lane < 17) && (p2 > SCORE_T);

    unsigned bal0 = __ballot_sync(0xFFFFFFFFu, val0);
    unsigned bal1 = __ballot_sync(0xFFFFFFFFu, val1);
    unsigned bal2 = __ballot_sync(0xFFFFFFFFu, val2);
    int n0 = __popc(bal0), n1 = __popc(bal1), n2 = __popc(bal2);
    int tot = n0 + n1 + n2;
    int base = 0;
    if (lane == 0 && tot) base = atomicAdd(&g_cnt, tot);
    base = __shfl_sync(0xFFFFFFFFu, base, 0);
    unsigned lmask = (1u << lane) - 1u;
    unsigned rowbase = (unsigned)warp * C_CLS;

    if (val0) {
        unsigned vb = __float_as_uint(p0);
        g_cand[base + __popc(bal0 & lmask)] =
            ((unsigned long long)vb << 32) | (0xFFFFFFFFu - (rowbase + lane));
        atomicAdd(&g_hist[(vb >> 16) - HIST_LO], 1u);
    }
    if (val1) {
        unsigned vb = __float_as_uint(p1);
        g_cand[base + n0 + __popc(bal1 & lmask)] =
            ((unsigned long long)vb << 32) | (0xFFFFFFFFu - (rowbase + lane + 32));
        atomicAdd(&g_hist[(vb >> 16) - HIST_LO], 1u);
    }
    if (val2) {
        unsigned vb = __float_as_uint(p2);
        g_cand[base + n0 + n1 + __popc(bal2 & lmask)] =
            ((unsigned long long)vb << 32) | (0xFFFFFFFFu - (rowbase + lane + 64));
        atomicAdd(&g_hist[(vb >> 16) - HIST_LO], 1u);
    }
}

// find cut bucket; also zero selCnt / rowAny for the downstream kernels
__global__ void k_findcut() {
    __shared__ unsigned int h[HIST_N];
    int t = threadIdx.x;
    if (t < HIST_N) h[t] = g_hist[t];
    if (t == 0) g_selCnt = 0;
    if (t < 64) g_rowAny[t] = 0ull;
    __syncthreads();
    if (t == 0) {
        unsigned int acc = 0;
        int b = HIST_N - 1;
        for (; b >= 0; b--) {
            acc += h[b];
            if (acc >= K_TOP) break;
        }
        g_cutBucket = (b < 0) ? 0 : b;
    }
}

__global__ void k_compact() {
    int cnt = g_cnt;
    int cut = g_cutBucket;
    int stride = gridDim.x * blockDim.x;
    for (int t = blockIdx.x * blockDim.x + threadIdx.x; t < cnt; t += stride) {
        unsigned long long key = g_cand[t];
        if ((int)((unsigned)(key >> 48) - HIST_LO) >= cut) {
            int pos = atomicAdd(&g_selCnt, 1);
            if (pos < SEL_MAX) g_sel[pos] = key;
        }
    }
}

// fused exact rank (descending, keys unique) + decode/scatter into final slot
__global__ void k_rankscatter(const float* __restrict__ boxes) {
    __shared__ unsigned long long tile[256];
    int m = g_selCnt; if (m > SEL_MAX) m = SEL_MAX;
    int i0 = blockIdx.x * 256;
    if (i0 >= m) return;                    // uniform per block
    int i = i0 + threadIdx.x;
    unsigned long long key = (i < m) ? g_sel[i] : 0ull;
    int cnt = 0;
    int ntile = (m + 255) >> 8;
    for (int tb = 0; tb < ntile; tb++) {
        int jt = tb * 256 + threadIdx.x;
        __syncthreads();
        tile[threadIdx.x] = (jt < m) ? g_sel[jt] : 0ull;
        __syncthreads();
        int lim = m - tb * 256; if (lim > 256) lim = 256;
        #pragma unroll 8
        for (int j = 0; j < lim; j++) cnt += (tile[j] > key);
    }
    if (i >= m || cnt >= K_TOP) return;
    int r = cnt;
    unsigned idx = 0xFFFFFFFFu - (unsigned)(key & 0xFFFFFFFFull);
    float val = __uint_as_float((unsigned)(key >> 32));
    int bi = (int)(idx / C_CLS);
    int lb = (int)(idx % C_CLS);
    float x1 = fminf(fmaxf(boxes[bi * 4 + 0], 0.0f), IMG_W - 1.0f);
    float y1 = fminf(fmaxf(boxes[bi * 4 + 1], 0.0f), IMG_H - 1.0f);
    float x2 = fminf(fmaxf(boxes[bi * 4 + 2], 0.0f), IMG_W - 1.0f);
    float y2 = fminf(fmaxf(boxes[bi * 4 + 3], 0.0f), IMG_H - 1.0f);
    g_bk[r][0] = x1; g_bk[r][1] = y1; g_bk[r][2] = x2; g_bk[r][3] = y2;
    g_val[r] = val; g_label[r] = lb;
    float off = __fmul_rn((float)lb, CLS_OFF);
    float ox1 = __fadd_rn(x1, off), oy1 = __fadd_rn(y1, off);
    float ox2 = __fadd_rn(x2, off), oy2 = __fadd_rn(y2, off);
    g_boff[r][0] = ox1; g_boff[r][1] = oy1; g_boff[r][2] = ox2; g_boff[r][3] = oy2;
    g_area[r] = __fmul_rn(__fsub_rn(ox2, ox1), __fsub_rn(oy2, oy1));
}

// suppression bitmask over the upper triangle only
__global__ void k_mask() {
    int q = blockIdx.x;
    int colB = (int)((sqrtf(8.0f * (float)q + 1.0f) - 1.0f) * 0.5f);
    while ((colB + 1) * (colB + 2) / 2 <= q) colB++;
    while (colB * (colB + 1) / 2 > q) colB--;
    int rowB = q - colB * (colB + 1) / 2;

    int t = threadIdx.x;  // 64 threads
    __shared__ float cb[64][4];
    __shared__ float ca[64];
    int j0 = colB * 64;
    cb[t][0] = g_boff[j0 + t][0]; cb[t][1] = g_boff[j0 + t][1];
    cb[t][2] = g_boff[j0 + t][2]; cb[t][3] = g_boff[j0 + t][3];
    ca[t] = g_area[j0 + t];
    __syncthreads();

    int i = rowB * 64 + t;
    unsigned long long w = 0ull;
    {
        float x1 = g_boff[i][0], y1 = g_boff[i][1], x2 = g_boff[i][2], y2 = g_boff[i][3];
        float ai = g_area[i];
        #pragma unroll 4
        for (int jj = 0; jj < 64; jj++) {
            int j = j0 + jj;
            if (j > i) {
                float iw = fmaxf(__fsub_rn(fminf(x2, cb[jj][2]), fmaxf(x1, cb[jj][0])), 0.0f);
                float ih = fmaxf(__fsub_rn(fminf(y2, cb[jj][3]), fmaxf(y1, cb[jj][1])), 0.0f);
                float inter = __fmul_rn(iw, ih);
                float denom = __fadd_rn(__fsub_rn(__fadd_rn(ai, ca[jj]), inter), 1e-9f);
                if (__fdiv_rn(inter, denom) > NMS_T) w |= (1ull << jj);
            }
        }
    }
    g_mask[(size_t)i * 64 + colB] = w;
    if (w) atomicOr(&g_rowAny[rowB], 1ull << t);
}

// Per-class parallel greedy NMS + output emit.
// Cross-class IoU is provably 0 (class offset 4096 > image extent), so the
// greedy recurrence splits into 80 independent chains — one warp per class.
__global__ void k_seqout(float* __restrict__ out, int out_size) {
    __shared__ unsigned long long s_removed[64];
    __shared__ int s_list[K_TOP];
    __shared__ unsigned char s_lab[K_TOP];
    __shared__ int s_cls[32][CLS_CAP];
    __shared__ int s_ofs[65];
    __shared__ int s_n;

    int t = threadIdx.x;
    int wid = t >> 5, lane = t & 31;

    if (t < 64) s_removed[t] = 0ull;
    // parallel list build: per-word counts, serial 64-prefix, parallel emit
    if (t < 64) s_ofs[t + 1] = __popcll(g_rowAny[t]);
    __syncthreads();
    if (t == 0) {
        s_ofs[0] = 0;
        for (int w = 0; w < 64; w++) s_ofs[w + 1] += s_ofs[w];
        s_n = s_ofs[64];
    }
    __syncthreads();
    if (t < 64) {
        unsigned long long bits = g_rowAny[t];
        int o = s_ofs[t];
        while (bits) {
            int b = __ffsll((long long)bits) - 1;
            bits &= bits - 1ull;
            s_list[o++] = t * 64 + b;
        }
    }
    __syncthreads();
    int n = s_n;
    for (int i = t; i < n; i += blockDim.x) s_lab[i] = (unsigned char)g_label[s_list[i]];
    __syncthreads();

    // warp wid handles classes c = 1+wid, 33+wid, 65+wid
    for (int c = 1 + wid; c < C_CLS; c += 32) {
        // compact this class's rows (ascending) into s_cls[wid]
        int k = 0;
        for (int base = 0; base < n; base += 32) {
            int ti = base + lane;
            bool mt = (ti < n) && (s_lab[ti] == (unsigned char)c);
            unsigned bal = __ballot_sync(0xFFFFFFFFu, mt);
            if (mt) {
                int pos = k + __popc(bal & ((1u << lane) - 1u));
                if (pos < CLS_CAP) s_cls[wid][pos] = s_list[ti];
            }
            k += __popc(bal);
        }
        if (k > CLS_CAP) k = CLS_CAP;
        if (k == 0) continue;

        // greedy chain over this class; removed bitmap distributed: lane owns words lane, lane+32
        unsigned long long rm0 = 0ull, rm1 = 0ull;
        for (int base = 0; base < k; base += 4) {
            unsigned long long m0[4], m1[4];
            int rows[4];
            #pragma unroll
            for (int j = 0; j < 4; j++) {
                int idx = base + j;
                int row = (idx < k) ? s_cls[wid][idx] : -1;
                rows[j] = row;
                m0[j] = (row >= 0) ? g_mask[(size_t)row * 64 + lane] : 0ull;
                m1[j] = (row >= 0) ? g_mask[(size_t)row * 64 + 32 + lane] : 0ull;
            }
            #pragma unroll
            for (int j = 0; j < 4; j++) {
                int row = rows[j];
                if (row < 0) break;   // uniform across warp
                int w = row >> 6;
                unsigned long long rv = (w < 32)
                    ? __shfl_sync(0xFFFFFFFFu, rm0, w)
                    : __shfl_sync(0xFFFFFFFFu, rm1, w - 32);
                if (!((rv >> (row & 63)) & 1ull)) { rm0 |= m0[j]; rm1 |= m1[j]; }
            }
        }
        if (rm0) atomicOr(&s_removed[lane], rm0);
        if (rm1) atomicOr(&s_removed[lane + 32], rm1);
    }
    __syncthreads();

    // emit output: dets[4096*5], labels[4096], keep[4096]
    for (int o = t; o < out_size; o += blockDim.x) {
        float v = 0.0f;
        if (o < K_TOP * 5) {
            int r = o / 5, c = o - r * 5;
            bool keep = !((s_removed[r >> 6] >> (r & 63)) & 1ull) && (g_val[r] > 0.0f);
            if (keep) v = (c < 4) ? g_bk[r][c] : g_val[r];
        } else if (o < K_TOP * 6) {
            v = (float)g_label[o - K_TOP * 5];
        } else if (o < K_TOP * 7) {
            int r = o - K_TOP * 6;
            bool keep = !((s_removed[r >> 6] >> (r & 63)) & 1ull) && (g_val[r] > 0.0f);
            v = keep ? 1.0f : 0.0f;
        }
        out[o] = v;
    }
}

extern "C" void kernel_launch(void* const* d_in, const int* in_sizes, int n_in,
                              void* d_out, int out_size) {
    const float* x     = (const float*)d_in[0];
    const float* boxes = (const float*)d_in[1];
    float* out = (float*)d_out;

    k_zero<<<1, 576>>>();
    k_softmax<<<N_BOX / 8, 256>>>(x);
    k_findcut<<<1, 576>>>();
    k_compact<<<512, 256>>>();
    k_rankscatter<<<SEL_MAX / 256, 256>>>(boxes);
    k_mask<<<65 * 64 / 2, 64>>>();
    k_seqout<<<1, 1024>>>(out, out_size);
}